// round 3
// baseline (speedup 1.0000x reference)
#include <cuda_runtime.h>

// OTAM soft-DTW cumulative distance, exp-domain formulation.
// dists: [256, 64, 48, 48] f32  ->  out: [256, 64] f32
//
// Log-domain reference per cell:
//   cur[m] = d[m] - lbda*ln( exp(-prev[m-1]/l) + exp(-cur[m-1]/l) (+ exp(-prev[m]/l) at m==1, m==M2-1) )
// Exp-domain (E = exp(-cur/lbda), lbda = 0.5):
//   E_cur[m] = w[m] * ( E_prev[m-1] + E_cur[m-1] (+ E_prev[m] at edges) ),  w = exp(-2 d)
// Row 0 is a cumulative product of w. Answer = -0.5*ln(E_final[49]).

#define LQ 48          // rows per problem
#define MQ 48          // real columns per problem (padded DP has 50)
#define TPB 128        // threads per CTA = problems per CTA
#define PITCH4 13      // float4 pitch per problem-row in smem (13*16 = 208 B, conflict-free)
#define NSTAGES 4
#define STAGE_F4 (TPB * PITCH4)                  // 1664 float4 per stage
#define SMEM_BYTES (NSTAGES * STAGE_F4 * 16)     // 106496 B

__device__ __forceinline__ float ex2f(float x) {
    float y; asm("ex2.approx.f32 %0, %1;" : "=f"(y) : "f"(x)); return y;
}
__device__ __forceinline__ float lg2f(float x) {
    float y; asm("lg2.approx.f32 %0, %1;" : "=f"(y) : "f"(x)); return y;
}
__device__ __forceinline__ void cp_async16(void* smem_dst, const void* gsrc) {
    unsigned s = (unsigned)__cvta_generic_to_shared(smem_dst);
    asm volatile("cp.async.cg.shared.global [%0], [%1], 16;\n" :: "r"(s), "l"(gsrc) : "memory");
}

extern __shared__ float4 smem4[];

// Stage row l for all 128 problems of this CTA into buffer sbuf.
// Flat chunk index i in [0,1536): p = i/12, j = i%12 -> global contiguous within
// each problem's 192B row segment => warp requests are ~fully coalesced.
__device__ __forceinline__ void issue_stage(const float* __restrict__ gbase,
                                            float4* __restrict__ sbuf,
                                            int l, int tid) {
#pragma unroll
    for (int k = 0; k < 12; k++) {
        int i = tid + k * TPB;
        int p = i / 12;
        int j = i - p * 12;
        const float* src = gbase + (size_t)p * (LQ * MQ) + l * MQ + j * 4;
        cp_async16(&sbuf[p * PITCH4 + j], src);
    }
}

__global__ void __launch_bounds__(TPB, 1)
otam_kernel(const float* __restrict__ dists, float* __restrict__ out) {
    const int tid = threadIdx.x;
    const int pbase = blockIdx.x * TPB;
    const float* gbase = dists + (size_t)pbase * (LQ * MQ);

    // Prologue: fill the pipeline.
#pragma unroll
    for (int s = 0; s < NSTAGES; s++) {
        issue_stage(gbase, smem4 + s * STAGE_F4, s, tid);
        asm volatile("cp.async.commit_group;\n" ::: "memory");
    }

    const float C = -2.885390081777927f;   // -2/ln2 : w = exp2(C*d) = exp(-2d)

    float E[50];                           // E[1..49] used: prev-row exp values

    for (int l = 0; l < LQ; l++) {
        // With one (possibly empty) commit per iteration, groups issued = l+4,
        // so wait_group 3 guarantees group l (row l) has landed.
        asm volatile("cp.async.wait_group 3;\n" ::: "memory");
        __syncthreads();

        const float4* rp = smem4 + (size_t)(l & (NSTAGES - 1)) * STAGE_F4 + tid * PITCH4;

        if (l == 0) {
            // Row 0: cumulative sum in log domain == cumulative product of w.
            float run = 1.f;
#pragma unroll
            for (int j = 0; j < 12; j++) {
                float4 q = rp[j];
                run *= ex2f(q.x * C); E[4 * j + 1] = run;
                run *= ex2f(q.y * C); E[4 * j + 2] = run;
                run *= ex2f(q.z * C); E[4 * j + 3] = run;
                run *= ex2f(q.w * C); E[4 * j + 4] = run;
            }
            E[49] = E[48];                 // pad column: d = 0 -> w = 1
        } else {
            float diag = 1.f;              // E_prev[0] == exp(0)
            float c = 1.f;                 // E_cur[0]  == exp(0)
#pragma unroll
            for (int j = 0; j < 12; j++) {
                float4 q = rp[j];
#define CELL(DV, MM, INC)                                          \
                {                                                  \
                    float t = E[MM];                               \
                    float s = diag + c;                            \
                    if (INC) s += t;                               \
                    c = ex2f((DV) * C) * s;                        \
                    diag = t;                                      \
                    E[MM] = c;                                     \
                }
                CELL(q.x, 4 * j + 1, (4 * j + 1) == 1)
                CELL(q.y, 4 * j + 2, false)
                CELL(q.z, 4 * j + 3, false)
                CELL(q.w, 4 * j + 4, false)
#undef CELL
            }
            // m = 49 (pad column): w = 1, edge includes E_prev[49].
            {
                float t = E[49];
                c = diag + c + t;
                E[49] = c;
            }
        }

        __syncthreads();                   // everyone done reading buffer (l & 3)
        if (l + NSTAGES < LQ)
            issue_stage(gbase, smem4 + ((l + NSTAGES) & (NSTAGES - 1)) * STAGE_F4,
                        l + NSTAGES, tid);
        asm volatile("cp.async.commit_group;\n" ::: "memory");  // empty group ok
    }

    // answer = -lbda * ln(E[49]) = -0.5*ln2 * log2(E[49])
    out[pbase + tid] = -0.34657359027997264f * lg2f(E[49]);
}

extern "C" void kernel_launch(void* const* d_in, const int* in_sizes, int n_in,
                              void* d_out, int out_size) {
    const float* dists = (const float*)d_in[0];
    float* out = (float*)d_out;
    int B = in_sizes[0] / (LQ * MQ);       // 16384 problems
    int grid = B / TPB;                    // 128 CTAs

    cudaFuncSetAttribute(otam_kernel, cudaFuncAttributeMaxDynamicSharedMemorySize,
                         SMEM_BYTES);
    otam_kernel<<<grid, TPB, SMEM_BYTES>>>(dists, out);
}

// round 8
// speedup vs baseline: 1.0750x; 1.0750x over previous
#include <cuda_runtime.h>

// OTAM soft-DTW, exp-domain, warp-autonomous streaming version.
// dists: [256, 64, 48, 48] f32 -> out: [256, 64] f32
//
// E = exp(-cum/lbda), lbda = 0.5:
//   E_cur[m] = w[m] * (E_prev[m-1] + E_cur[m-1] (+ E_prev[m] at m==1, m==49)),
//   w = exp(-2 d) = exp2(C*d).  Row 0 is a cumprod of w.
//   answer = -0.5*ln(E_final[49]).
//
// One warp per CTA, 32 problems per warp (1 per lane), grid = 512 so all 148
// SMs are busy. Each warp runs a private 6-stage cp.async ring with only
// warp-level sync -> no CTA barriers, DRAM streams continuously.

#define LQ 48
#define MQ 48
#define PPW 32                               // problems per warp/CTA
#define PITCH4 13                            // float4 pitch (208 B) -> LDS.128 conflict-free
#define NSTAGES 6
#define STAGE_F4 (PPW * PITCH4)              // 416 float4 = 6656 B per stage
#define SMEM_BYTES (NSTAGES * STAGE_F4 * 16) // 39936 B per CTA

__device__ __forceinline__ float ex2f(float x) {
    float y; asm("ex2.approx.f32 %0, %1;" : "=f"(y) : "f"(x)); return y;
}
__device__ __forceinline__ float lg2f(float x) {
    float y; asm("lg2.approx.f32 %0, %1;" : "=f"(y) : "f"(x)); return y;
}
__device__ __forceinline__ void cp_async16(void* smem_dst, const void* gsrc) {
    unsigned s = (unsigned)__cvta_generic_to_shared(smem_dst);
    asm volatile("cp.async.cg.shared.global [%0], [%1], 16;\n" :: "r"(s), "l"(gsrc) : "memory");
}

extern __shared__ float4 smem4[];

// Stage row l of this warp's 32 problems. 384 16B chunks, 12 per lane.
// Chunks are contiguous within each problem's 192B row segment -> fully
// coalesced (6 full 32B sectors per problem-row).
__device__ __forceinline__ void issue_stage(const float* __restrict__ gbase,
                                            float4* __restrict__ sbuf,
                                            int l, int lane) {
#pragma unroll
    for (int k = 0; k < 12; k++) {
        int ch = lane + k * 32;
        int p = ch / 12;
        int j = ch - p * 12;
        cp_async16(&sbuf[p * PITCH4 + j],
                   gbase + (size_t)p * (LQ * MQ) + l * MQ + j * 4);
    }
}

__global__ void __launch_bounds__(32, 1)
otam_kernel(const float* __restrict__ dists, float* __restrict__ out) {
    const int lane = threadIdx.x;
    const int pbase = blockIdx.x * PPW;
    const float* gbase = dists + (size_t)pbase * (LQ * MQ);

    // Prologue: fill the ring.
#pragma unroll
    for (int s = 0; s < NSTAGES; s++) {
        issue_stage(gbase, smem4 + s * STAGE_F4, s, lane);
        asm volatile("cp.async.commit_group;\n" ::: "memory");
    }

    const float C = -2.885390081777927f;   // -2/ln2 : exp2(C*d) = exp(-2d)
    float E[50];                           // prev-row exp values, E[1..49]
    int buf = 0;

    for (int l = 0; l < LQ; l++) {
        // One (possibly empty) commit per row -> wait_group NSTAGES-1 means
        // the group carrying row l has landed.
        asm volatile("cp.async.wait_group %0;\n" :: "n"(NSTAGES - 1) : "memory");
        __syncwarp();                      // make all lanes' copies visible

        const float4* rp = smem4 + buf * STAGE_F4 + lane * PITCH4;

        if (l == 0) {
            float run = 1.f;
#pragma unroll
            for (int j = 0; j < 12; j++) {
                float4 q = rp[j];
                run *= ex2f(q.x * C); E[4 * j + 1] = run;
                run *= ex2f(q.y * C); E[4 * j + 2] = run;
                run *= ex2f(q.z * C); E[4 * j + 3] = run;
                run *= ex2f(q.w * C); E[4 * j + 4] = run;
            }
            E[49] = E[48];                 // pad column: d = 0 -> w = 1
        } else {
            float diag = 1.f;              // E_prev[m-1], starts at exp(0)
            float c = 1.f;                 // E_cur[0] = exp(0)
#pragma unroll
            for (int j = 0; j < 12; j++) {
                float4 q = rp[j];
                float w0 = ex2f(q.x * C);
                float w1 = ex2f(q.y * C);
                float w2 = ex2f(q.z * C);
                float w3 = ex2f(q.w * C);
                // single-FFMA chain: c = fma(w, c, w*diag); w*diag off-chain
#define CELL(W, MM)                                                  \
                { float t = E[MM]; float wd = (W) * diag;            \
                  c = fmaf((W), c, wd); diag = t; E[MM] = c; }
                if (j == 0) {
                    // m == 1 edge: includes E_prev[1]; diag = c = 1 here.
                    float t = E[1];
                    c = w0 * (2.f + t);
                    diag = t; E[1] = c;
                } else {
                    CELL(w0, 4 * j + 1)
                }
                CELL(w1, 4 * j + 2)
                CELL(w2, 4 * j + 3)
                CELL(w3, 4 * j + 4)
#undef CELL
            }
            // m == 49 pad column: w = 1, edge includes E_prev[49].
            { float t = E[49]; c = diag + c + t; E[49] = c; }
        }

        __syncwarp();                      // all lanes done reading this buffer
        if (l + NSTAGES < LQ)
            issue_stage(gbase, smem4 + buf * STAGE_F4, l + NSTAGES, lane);
        asm volatile("cp.async.commit_group;\n" ::: "memory");  // empty ok

        buf = (buf + 1 == NSTAGES) ? 0 : buf + 1;
    }

    out[pbase + lane] = -0.34657359027997264f * lg2f(E[49]);
}

extern "C" void kernel_launch(void* const* d_in, const int* in_sizes, int n_in,
                              void* d_out, int out_size) {
    const float* dists = (const float*)d_in[0];
    float* out = (float*)d_out;
    int B = in_sizes[0] / (LQ * MQ);       // 16384 problems
    int grid = B / PPW;                    // 512 CTAs (1 warp each)

    cudaFuncSetAttribute(otam_kernel, cudaFuncAttributeMaxDynamicSharedMemorySize,
                         SMEM_BYTES);
    otam_kernel<<<grid, 32, SMEM_BYTES>>>(dists, out);
}